// round 16
// baseline (speedup 1.0000x reference)
#include <cuda_runtime.h>

// Fused autoencoder forward + Jacobians.
// R15 (direct-domain activation, LDCU.128 weights) + __launch_bounds__(256,3)
// to hold 3 CTAs/SM resident (R15's 84 regs crossed an RF-granularity boundary
// and halved occupancy; capping at ~85 regs restores it).
// Outputs: theta[N,2] | J_h[N,2,2] | q_hat[N,2] | J_h_dec[N,2,2] | J_h_ana[N,2,2]

typedef unsigned long long pf;   // packed (lo,hi) f32 pair
union PU { pf u; float2 f; };
union QU { float4 q; struct { pf lo, hi; } p; };

__device__ __forceinline__ pf pk(float2 v)   { PU c; c.f = v; return c.u; }
__device__ __forceinline__ pf dup2(float v)  { PU c; c.f = make_float2(v, v); return c.u; }
__device__ __forceinline__ float2 up(pf u)   { PU c; c.u = u; return c.f; }
__device__ __forceinline__ pf ffma2(pf a, pf b, pf c) {
    pf d; asm("fma.rn.f32x2 %0, %1, %2, %3;" : "=l"(d) : "l"(a), "l"(b), "l"(c)); return d;
}
__device__ __forceinline__ pf fmul2(pf a, pf b) {
    pf d; asm("mul.rn.f32x2 %0, %1, %2;" : "=l"(d) : "l"(a), "l"(b)); return d;
}

struct CData {
    float4 w2q[2][128];  // [j*8+p] = (dup w2[j][2p], dup w2[j][2p+1])
    float4 w3q[2][16];   // [j] = (w30 dup, w31 dup)
    float2 w1p[2][16];   // natural (w0,w1) rows of W1
    float  b1[2][16];
    float  b2[2][16];
    float  b3[2][2];
};

__constant__ CData CW;
__device__   CData g_scratch;

// Direct-domain softplus + sigmoid (z bounded |z|<~14 for this model):
//   t = e^z ; u = 1+t ; h = lg2(u)*ln2 ; s = t*rcp(u)
// 4 fixed ops + 3 MUFU; lg2 and rcp independent (short critical path).
__device__ __forceinline__ void act(float z, float& h, float& s) {
    const float L2E = 1.442695041f, LN2 = 0.6931471806f;
    float t, g, r;
    asm("ex2.approx.ftz.f32 %0, %1;" : "=f"(t) : "f"(z * L2E));   // e^z
    float u = 1.0f + t;
    asm("lg2.approx.ftz.f32 %0, %1;" : "=f"(g) : "f"(u));
    asm("rcp.approx.ftz.f32 %0, %1;" : "=f"(r) : "f"(u));
    h = g * LN2;
    s = t * r;
}

// MLP 2->16->16->2 softplus. Forward values scalar; Jacobian rows packed:
// rj0=(J00,J01), rj1=(J10,J11).  E=0 encoder, E=1 decoder.
template<int E>
__device__ __forceinline__ void mlp_jac(
    float x0, float x1,
    float& y0, float& y1, pf& rj0, pf& rj1)
{
    float h[16];
    pf tab[16];
#pragma unroll
    for (int i = 0; i < 16; ++i) {
        float2 w = CW.w1p[E][i];
        float z = fmaf(w.x, x0, fmaf(w.y, x1, CW.b1[E][i]));
        float hh, s;
        act(z, hh, s);
        h[i]   = hh;
        tab[i] = fmul2(dup2(s), pk(w));   // (ta,tb) = s*(w0,w1)
    }

    float acc0 = CW.b3[E][0], acc1 = CW.b3[E][1];
    pf j0 = 0, j1 = 0;                    // (J00,J01), (J10,J11)
#pragma unroll
    for (int j = 0; j < 16; ++j) {
        float z = CW.b2[E][j];
        pf ab = 0;
#pragma unroll
        for (int p = 0; p < 8; ++p) {
            QU w; w.q = CW.w2q[E][8 * j + p];   // one LDCU.128
            z  = fmaf(w.q.x, h[2 * p],     z);
            ab = ffma2(w.p.lo, tab[2 * p],     ab);
            z  = fmaf(w.q.z, h[2 * p + 1], z);
            ab = ffma2(w.p.hi, tab[2 * p + 1], ab);
        }
        float hh, s;
        act(z, hh, s);
        pf sab = fmul2(dup2(s), ab);          // (s*a, s*b)
        QU w3; w3.q = CW.w3q[E][j];            // one LDCU.128
        acc0 = fmaf(w3.q.x, hh, acc0);
        acc1 = fmaf(w3.q.z, hh, acc1);
        j0 = ffma2(w3.p.lo, sab, j0);
        j1 = ffma2(w3.p.hi, sab, j1);
    }
    y0 = acc0; y1 = acc1; rj0 = j0; rj1 = j1;
}

__global__ void __launch_bounds__(256) prep_kernel(
    const float* __restrict__ ew1, const float* __restrict__ eb1,
    const float* __restrict__ ew2, const float* __restrict__ eb2,
    const float* __restrict__ ew3, const float* __restrict__ eb3,
    const float* __restrict__ dw1, const float* __restrict__ db1,
    const float* __restrict__ dw2, const float* __restrict__ db2,
    const float* __restrict__ dw3, const float* __restrict__ db3)
{
    const int t = threadIdx.x;
    const float* W1[2] = {ew1, dw1};
    const float* B1[2] = {eb1, db1};
    const float* W2[2] = {ew2, dw2};
    const float* B2[2] = {eb2, db2};
    const float* W3[2] = {ew3, dw3};
    const float* B3[2] = {eb3, db3};

#pragma unroll
    for (int E = 0; E < 2; ++E) {
        if (t < 128) {
            int j = t >> 3, p = t & 7;
            float wa = W2[E][j * 16 + 2 * p];
            float wb = W2[E][j * 16 + 2 * p + 1];
            g_scratch.w2q[E][t] = make_float4(wa, wa, wb, wb);
        }
        if (t < 16) {
            float w30 = W3[E][t], w31 = W3[E][16 + t];
            g_scratch.w3q[E][t] = make_float4(w30, w30, w31, w31);
            g_scratch.w1p[E][t] = make_float2(W1[E][2 * t], W1[E][2 * t + 1]);
            g_scratch.b1[E][t] = B1[E][t];
            g_scratch.b2[E][t] = B2[E][t];
        }
        if (t < 2) g_scratch.b3[E][t] = B3[E][t];
    }
}

__global__ void __launch_bounds__(256, 3) ae_kernel(
    const float* __restrict__ q, float* __restrict__ out, int N)
{
    const int n = blockIdx.x * 256 + threadIdx.x;
    if (n >= N) return;

    const float2 qv = reinterpret_cast<const float2*>(q)[n];
    const float q0 = qv.x, q1 = qv.y;

    // analytic jacobian
    const float r2  = fmaf(q0, q0, q1 * q1);
    const float inv = __fdividef(1.0f, r2);
    const float isr = rsqrtf(r2 + 1e-8f);
    const float ja00 = -q1 * inv;
    const float ja01 =  q0 * inv;
    const float ja10 =  q0 * isr;
    const float ja11 =  q1 * isr;

    float th0, th1, qh0, qh1;
    pf jh0, jh1, jd0, jd1;
    mlp_jac<0>(q0, q1, th0, th1, jh0, jh1);
    mlp_jac<1>(th0, th1, qh0, qh1, jd0, jd1);

    const size_t Ns = (size_t)N;
    float2* o_theta = reinterpret_cast<float2*>(out);
    pf*     o_jh    = reinterpret_cast<pf*>(out + 2 * Ns);
    float2* o_qhat  = reinterpret_cast<float2*>(out + 6 * Ns);
    pf*     o_jd    = reinterpret_cast<pf*>(out + 8 * Ns);
    float4* o_ja    = reinterpret_cast<float4*>(out + 12 * Ns);

    o_theta[n]      = make_float2(th0, th1);
    o_jh[2 * n]     = jh0;               // (J00,J01)
    o_jh[2 * n + 1] = jh1;               // (J10,J11)
    o_qhat[n]       = make_float2(qh0, qh1);
    o_jd[2 * n]     = jd0;
    o_jd[2 * n + 1] = jd1;
    o_ja[n]         = make_float4(ja00, ja01, ja10, ja11);
}

extern "C" void kernel_launch(void* const* d_in, const int* in_sizes, int n_in,
                              void* d_out, int out_size) {
    const float* q = (const float*)d_in[0];

    prep_kernel<<<1, 256>>>(
        (const float*)d_in[1], (const float*)d_in[2],
        (const float*)d_in[3], (const float*)d_in[4],
        (const float*)d_in[5], (const float*)d_in[6],
        (const float*)d_in[7], (const float*)d_in[8],
        (const float*)d_in[9], (const float*)d_in[10],
        (const float*)d_in[11], (const float*)d_in[12]);

    void* cw_addr = nullptr;
    void* sc_addr = nullptr;
    cudaGetSymbolAddress(&cw_addr, CW);
    cudaGetSymbolAddress(&sc_addr, g_scratch);
    cudaMemcpyAsync(cw_addr, sc_addr, sizeof(CData),
                    cudaMemcpyDeviceToDevice, 0);

    const int N = in_sizes[0] / 2;
    const int blocks = (N + 255) / 256;
    ae_kernel<<<blocks, 256>>>(q, (float*)d_out, N);
}

// round 17
// speedup vs baseline: 1.0252x; 1.0252x over previous
#include <cuda_runtime.h>

// FINAL: Fused autoencoder forward + Jacobians (best-measured config, R14).
// 1 sample/thread; scalar value chain + f32x2-packed tangent pair (ta,tb).
// Weights in __constant__, packed so each inner fetch is one 128-bit LDCU:
//   w2q[j*8+p] = (dup w2[j][2p], dup w2[j][2p+1])
//   w3q[j]     = (w3[0][j] dup, w3[1][j] dup)
// Outputs: theta[N,2] | J_h[N,2,2] | q_hat[N,2] | J_h_dec[N,2,2] | J_h_ana[N,2,2]

typedef unsigned long long pf;   // packed (lo,hi) f32 pair
union PU { pf u; float2 f; };
union QU { float4 q; struct { pf lo, hi; } p; };

__device__ __forceinline__ pf pk(float2 v)   { PU c; c.f = v; return c.u; }
__device__ __forceinline__ pf dup2(float v)  { PU c; c.f = make_float2(v, v); return c.u; }
__device__ __forceinline__ float2 up(pf u)   { PU c; c.u = u; return c.f; }
__device__ __forceinline__ pf ffma2(pf a, pf b, pf c) {
    pf d; asm("fma.rn.f32x2 %0, %1, %2, %3;" : "=l"(d) : "l"(a), "l"(b), "l"(c)); return d;
}
__device__ __forceinline__ pf fmul2(pf a, pf b) {
    pf d; asm("mul.rn.f32x2 %0, %1, %2;" : "=l"(d) : "l"(a), "l"(b)); return d;
}

struct CData {
    float4 w2q[2][128];  // [j*8+p] = (dup w2[j][2p], dup w2[j][2p+1])
    float4 w3q[2][16];   // [j] = (w30 dup, w31 dup)
    float2 w1p[2][16];   // natural (w0,w1) rows of W1
    float  b1[2][16];
    float  b2[2][16];
    float  b3[2][2];
};

__constant__ CData CW;
__device__   CData g_scratch;

// softplus h and sigmoid s (stable, 3 MUFU)
__device__ __forceinline__ void act(float z, float& h, float& s) {
    const float L2E = 1.442695041f, LN2 = 0.6931471806f;
    float t, g;
    asm("ex2.approx.ftz.f32 %0, %1;" : "=f"(t) : "f"(fabsf(z) * -L2E));
    asm("lg2.approx.ftz.f32 %0, %1;" : "=f"(g) : "f"(1.0f + t));
    h = fmaf(g, LN2, fmaxf(z, 0.0f));
    asm("ex2.approx.ftz.f32 %0, %1;" : "=f"(s) : "f"(fmaf(fminf(z, 0.0f), L2E, -g)));
}

// MLP 2->16->16->2 softplus. Forward values scalar; Jacobian rows packed:
// rj0=(J00,J01), rj1=(J10,J11).  E=0 encoder, E=1 decoder.
template<int E>
__device__ __forceinline__ void mlp_jac(
    float x0, float x1,
    float& y0, float& y1, pf& rj0, pf& rj1)
{
    float h[16];
    pf tab[16];
#pragma unroll
    for (int i = 0; i < 16; ++i) {
        float2 w = CW.w1p[E][i];
        float z = fmaf(w.x, x0, fmaf(w.y, x1, CW.b1[E][i]));
        float hh, s;
        act(z, hh, s);
        h[i]   = hh;
        tab[i] = fmul2(dup2(s), pk(w));   // (ta,tb) = s*(w0,w1)
    }

    float acc0 = CW.b3[E][0], acc1 = CW.b3[E][1];
    pf j0 = 0, j1 = 0;                    // (J00,J01), (J10,J11)
#pragma unroll
    for (int j = 0; j < 16; ++j) {
        float z = CW.b2[E][j];
        pf ab = 0;
#pragma unroll
        for (int p = 0; p < 8; ++p) {
            QU w; w.q = CW.w2q[E][8 * j + p];   // one LDCU.128
            z  = fmaf(w.q.x, h[2 * p],     z);
            ab = ffma2(w.p.lo, tab[2 * p],     ab);
            z  = fmaf(w.q.z, h[2 * p + 1], z);
            ab = ffma2(w.p.hi, tab[2 * p + 1], ab);
        }
        float hh, s;
        act(z, hh, s);
        pf sab = fmul2(dup2(s), ab);          // (s*a, s*b)
        QU w3; w3.q = CW.w3q[E][j];            // one LDCU.128
        acc0 = fmaf(w3.q.x, hh, acc0);
        acc1 = fmaf(w3.q.z, hh, acc1);
        j0 = ffma2(w3.p.lo, sab, j0);
        j1 = ffma2(w3.p.hi, sab, j1);
    }
    y0 = acc0; y1 = acc1; rj0 = j0; rj1 = j1;
}

__global__ void __launch_bounds__(256) prep_kernel(
    const float* __restrict__ ew1, const float* __restrict__ eb1,
    const float* __restrict__ ew2, const float* __restrict__ eb2,
    const float* __restrict__ ew3, const float* __restrict__ eb3,
    const float* __restrict__ dw1, const float* __restrict__ db1,
    const float* __restrict__ dw2, const float* __restrict__ db2,
    const float* __restrict__ dw3, const float* __restrict__ db3)
{
    const int t = threadIdx.x;
    const float* W1[2] = {ew1, dw1};
    const float* B1[2] = {eb1, db1};
    const float* W2[2] = {ew2, dw2};
    const float* B2[2] = {eb2, db2};
    const float* W3[2] = {ew3, dw3};
    const float* B3[2] = {eb3, db3};

#pragma unroll
    for (int E = 0; E < 2; ++E) {
        if (t < 128) {
            int j = t >> 3, p = t & 7;
            float wa = W2[E][j * 16 + 2 * p];
            float wb = W2[E][j * 16 + 2 * p + 1];
            g_scratch.w2q[E][t] = make_float4(wa, wa, wb, wb);
        }
        if (t < 16) {
            float w30 = W3[E][t], w31 = W3[E][16 + t];
            g_scratch.w3q[E][t] = make_float4(w30, w30, w31, w31);
            g_scratch.w1p[E][t] = make_float2(W1[E][2 * t], W1[E][2 * t + 1]);
            g_scratch.b1[E][t] = B1[E][t];
            g_scratch.b2[E][t] = B2[E][t];
        }
        if (t < 2) g_scratch.b3[E][t] = B3[E][t];
    }
}

__global__ void __launch_bounds__(256) ae_kernel(
    const float* __restrict__ q, float* __restrict__ out, int N)
{
    const int n = blockIdx.x * 256 + threadIdx.x;
    if (n >= N) return;

    const float2 qv = reinterpret_cast<const float2*>(q)[n];
    const float q0 = qv.x, q1 = qv.y;

    // analytic jacobian
    const float r2  = fmaf(q0, q0, q1 * q1);
    const float inv = __fdividef(1.0f, r2);
    const float isr = rsqrtf(r2 + 1e-8f);
    const float ja00 = -q1 * inv;
    const float ja01 =  q0 * inv;
    const float ja10 =  q0 * isr;
    const float ja11 =  q1 * isr;

    float th0, th1, qh0, qh1;
    pf jh0, jh1, jd0, jd1;
    mlp_jac<0>(q0, q1, th0, th1, jh0, jh1);
    mlp_jac<1>(th0, th1, qh0, qh1, jd0, jd1);

    const size_t Ns = (size_t)N;
    float2* o_theta = reinterpret_cast<float2*>(out);
    pf*     o_jh    = reinterpret_cast<pf*>(out + 2 * Ns);
    float2* o_qhat  = reinterpret_cast<float2*>(out + 6 * Ns);
    pf*     o_jd    = reinterpret_cast<pf*>(out + 8 * Ns);
    float4* o_ja    = reinterpret_cast<float4*>(out + 12 * Ns);

    o_theta[n]      = make_float2(th0, th1);
    o_jh[2 * n]     = jh0;               // (J00,J01)
    o_jh[2 * n + 1] = jh1;               // (J10,J11)
    o_qhat[n]       = make_float2(qh0, qh1);
    o_jd[2 * n]     = jd0;
    o_jd[2 * n + 1] = jd1;
    o_ja[n]         = make_float4(ja00, ja01, ja10, ja11);
}

extern "C" void kernel_launch(void* const* d_in, const int* in_sizes, int n_in,
                              void* d_out, int out_size) {
    const float* q = (const float*)d_in[0];

    prep_kernel<<<1, 256>>>(
        (const float*)d_in[1], (const float*)d_in[2],
        (const float*)d_in[3], (const float*)d_in[4],
        (const float*)d_in[5], (const float*)d_in[6],
        (const float*)d_in[7], (const float*)d_in[8],
        (const float*)d_in[9], (const float*)d_in[10],
        (const float*)d_in[11], (const float*)d_in[12]);

    void* cw_addr = nullptr;
    void* sc_addr = nullptr;
    cudaGetSymbolAddress(&cw_addr, CW);
    cudaGetSymbolAddress(&sc_addr, g_scratch);
    cudaMemcpyAsync(cw_addr, sc_addr, sizeof(CData),
                    cudaMemcpyDeviceToDevice, 0);

    const int N = in_sizes[0] / 2;
    const int blocks = (N + 255) / 256;
    ae_kernel<<<blocks, 256>>>(q, (float*)d_out, N);
}